// round 17
// baseline (speedup 1.0000x reference)
#include <cuda_runtime.h>
#include <cstdint>

// Soft Smith-Waterman, linear (exp) domain, 8x8 row-blocked wavefront,
// per-lane exponent renorm, batched acquire/release edge protocol
// (R14-proven). CO-LOCATED BATCHES: one CTA per band holds 8 warps = the 8
// independent batches (2 warps per SMSP -> sibling warp fills dependency
// stalls). No intra-CTA synchronization; smem is partitioned per warp.
// X = exp(H):  X = 1 + e^s * Xdiag + e^-1 * (Xup + Xleft)
// Lane l owns cols 8l..8l+7 of its 256-col band; computes 8 rows x 8 cols
// per step, staggered 1 step/lane. 8 band-CTAs x 8 batch-warps = 64 warps.

#define MM 2048
#define NN 2048
#define RB 8
#define BANDW 256
#define NB 8
#define NROWBLK 256
#define NSTEP 287
#define SLACK 16
#define WARP_F4 1536                        // 3 slots * 8 rows * 2 h * 32 lanes
#define SMEM_BYTES (8 * WARP_F4 * 16)       // 196608 B = 192 KB
#define LN2   0.6931471805599453f
#define LOG2E 1.4426950408889634f
#define EG    0.36787944117144233f          // e^-1

__device__ float g_edgeY[8][NB][MM];        // edge Y per row
__device__ int   g_edgeK[8][NB][NROWBLK];   // edge K per 8-row group
__device__ int   g_flag[8][NB];
__device__ int   g_max[8];

static __device__ __forceinline__ float ex2f(float x) {
    float r; asm("ex2.approx.f32 %0, %1;" : "=f"(r) : "f"(x)); return r;
}
static __device__ __forceinline__ float lg2f(float x) {
    float r; asm("lg2.approx.f32 %0, %1;" : "=f"(r) : "f"(x)); return r;
}
static __device__ __forceinline__ int ld_acq(const int* p) {
    int v; asm volatile("ld.global.acquire.gpu.b32 %0, [%1];" : "=r"(v) : "l"(p)); return v;
}
static __device__ __forceinline__ void st_rel(int* p, int v) {
    asm volatile("st.global.release.gpu.b32 [%0], %1;" :: "l"(p), "r"(v) : "memory");
}
static __device__ __forceinline__ float4 ldcg4(const float4* p) {
    float4 v;
    asm volatile("ld.global.cg.v4.f32 {%0,%1,%2,%3}, [%4];"
                 : "=f"(v.x), "=f"(v.y), "=f"(v.z), "=f"(v.w) : "l"(p));
    return v;
}
static __device__ __forceinline__ int4 ldcg4i(const int4* p) {
    int4 v;
    asm volatile("ld.global.cg.v4.b32 {%0,%1,%2,%3}, [%4];"
                 : "=r"(v.x), "=r"(v.y), "=r"(v.z), "=r"(v.w) : "l"(p));
    return v;
}
static __device__ __forceinline__ void stcg4(float4* p, float4 v) {
    asm volatile("st.global.cg.v4.f32 [%0], {%1,%2,%3,%4};"
                 :: "l"(p), "f"(v.x), "f"(v.y), "f"(v.z), "f"(v.w) : "memory");
}
static __device__ __forceinline__ void stcg_i(int* p, int v) {
    asm volatile("st.global.cg.b32 [%0], %1;" :: "l"(p), "r"(v) : "memory");
}
static __device__ __forceinline__ void cp16(uint32_t dst, const void* src) {
    asm volatile("cp.async.cg.shared.global [%0], [%1], 16;" :: "r"(dst), "l"(src));
}
static __device__ __forceinline__ void cp_commit() {
    asm volatile("cp.async.commit_group;" ::: "memory");
}
template <int N> static __device__ __forceinline__ void cp_wait() {
    asm volatile("cp.async.wait_group %0;" :: "n"(N) : "memory");
}
static __device__ __forceinline__ float pow2i(int k) {   // 2^k, k in [-126,127]
    return __int_as_float((127 + k) << 23);
}

__global__ void sw_init_kernel() {
    int i = threadIdx.x;
    if (i < 8 * NB) ((int*)g_flag)[i] = 0;
    if (i < 8) g_max[i] = 0;    // bits of 0.0f; H >= 0
}

__global__ void __launch_bounds__(256, 1)
sw_wave_kernel(const float* __restrict__ S) {
    extern __shared__ float4 stile[];   // [warp8][slot3][row8][h2][lane32]

    const int w = blockIdx.x;           // band
    const int b = threadIdx.x >> 5;     // batch = warp id (0..7)
    const int l = threadIdx.x & 31;

    const float* Sl = S + (size_t)b * MM * NN + (size_t)w * BANDW + (size_t)l * 8;
    const int*   flagp   = (w > 0) ? &g_flag[b][w - 1]  : (const int*)0;
    const float* edgeYp  = (w > 0) ? g_edgeY[b][w - 1]  : (const float*)0;
    const int*   edgeKp  = (w > 0) ? g_edgeK[b][w - 1]  : (const int*)0;
    float*       myedgeY = g_edgeY[b][w];
    int*         myedgeK = g_edgeK[b][w];
    int*         myflag  = &g_flag[b][w];
    const bool   produce = (w != NB - 1);

    const int wbase = b * WARP_F4;      // this warp's smem slice (float4 units)
    const uint32_t smem_u32 =
        (uint32_t)__cvta_generic_to_shared(&stile[wbase]);

    float B[8];
    #pragma unroll
    for (int j = 0; j < 8; ++j) B[j] = 1.f;
    float yR[8];
    #pragma unroll
    for (int j = 0; j < 8; ++j) yR[j] = 1.f;
    float y7p = 1.f, ecarry = 1.f, C = 1.f;
    float Ymax = 0.f, vh = 0.f;
    int   Ki = 0;
    int   flag_seen = 0;
    float4 YQ[8];
    int4   K4 = {0, 0, 0, 0};

#define ISSUE_SLOT(SS, SLOT) { \
    int r0_ = RB * ((SS) - l); \
    r0_ = max(0, min(MM - RB, r0_)); \
    const float* src_ = Sl + (size_t)r0_ * NN; \
    _Pragma("unroll") for (int rr = 0; rr < RB; ++rr) { \
        uint32_t d_ = smem_u32 + ((((SLOT) * RB + rr) * 2) * 32 + l) * 16; \
        const float* sr_ = src_ + (size_t)rr * NN; \
        cp16(d_, sr_);  cp16(d_ + 512, sr_ + 4); } \
    cp_commit(); }

    ISSUE_SLOT(0, 0)
    ISSUE_SLOT(1, 1)

    // Startup slack so steady-state batch acquires return immediately.
    if (w > 0) { while (flag_seen < SLACK) flag_seen = ld_acq(flagp); }

    int sl_cur = 0, sl_iss = 2;
    for (int sb = 0; sb < NSTEP; sb += 4) {
        // ---- per-lane renorm every 4 steps (32 rows) ----
        if (sb != 0) {
            float m_ = B[0];
            #pragma unroll
            for (int j = 1; j < 8; ++j) m_ = fmaxf(m_, B[j]);
            int k_ = (__float_as_int(m_) >> 23) - 127;    // m_ > 0 always
            float sc_ = pow2i(-k_);
            vh = fmaxf(vh, lg2f(Ymax) + (float)Ki);
            Ymax = 0.f; Ki += k_; C *= sc_;
            #pragma unroll
            for (int j = 0; j < 8; ++j) { B[j] *= sc_; yR[j] *= sc_; }
            y7p *= sc_; ecarry *= sc_;
        }

        // ---- batched edge intake: one acquire + 32 rows per 4 steps ----
        const bool eb = (w > 0) && (sb < NROWBLK);
        if (eb) {
            const int need = min(sb + 4, NROWBLK);
            while (flag_seen < need) flag_seen = ld_acq(flagp);
            const float4* yp = (const float4*)(edgeYp + RB * sb);
            #pragma unroll
            for (int q = 0; q < 8; ++q) YQ[q] = ldcg4(yp + q);
            K4 = ldcg4i((const int4*)(edgeKp + (sb >> 0)));
        }

        #pragma unroll
        for (int j = 0; j < 4; ++j) {
            const int s = sb + j;
            if (s >= NSTEP) break;

            // ---- score pipeline: issue slot s+2, ensure slot s resident ----
            ISSUE_SLOT(s + 2, sl_iss)
            cp_wait<2>();

            // ---- edge conversion for this step (Ki constant in batch) ----
            float e_[8];
            if (eb && s < NROWBLK) {
                const int kj = (j == 0) ? K4.x : (j == 1) ? K4.y
                             : (j == 2) ? K4.z : K4.w;
                const float fs = pow2i(max(-126, min(127, kj - Ki)));
                float4 ya = YQ[2 * j], yb = YQ[2 * j + 1];
                e_[0] = ya.x * fs; e_[1] = ya.y * fs;
                e_[2] = ya.z * fs; e_[3] = ya.w * fs;
                e_[4] = yb.x * fs; e_[5] = yb.y * fs;
                e_[6] = yb.z * fs; e_[7] = yb.w * fs;
            } else {
                #pragma unroll
                for (int t = 0; t < 8; ++t) e_[t] = C;
            }

            // ---- neighbor exchange with per-lane rescale 2^(K[l-1]-K[l]) ----
            int kk_ = __shfl_up_sync(0xffffffffu, Ki, 1);
            float fs_ = pow2i(max(-126, min(127, kk_ - Ki)));
            float Lf[8]; float Ld;
            #pragma unroll
            for (int t = 0; t < 8; ++t) {
                float tv = __shfl_up_sync(0xffffffffu, yR[t], 1);
                Lf[t] = (l == 0) ? e_[t] : tv * fs_;
            }
            { float tv = __shfl_up_sync(0xffffffffu, y7p, 1);
              Ld = (l == 0) ? ecarry : tv * fs_; }
            ecarry = e_[7];

            const bool valid_ = (s >= l) && (s - l < NROWBLK);
            const bool z_ = (s == l);
            if (z_) Ld = C;
            #pragma unroll
            for (int t = 0; t < 8; ++t) if (z_) B[t] = C;

            // ---- 8x8 block, in-loop ex2 ----
            float dc_ = Ld, ymx_ = 0.f;
            #pragma unroll
            for (int h = 0; h < 2; ++h) {
                float4 sq[8];
                #pragma unroll
                for (int t = 0; t < 8; ++t)
                    sq[t] = stile[wbase + ((sl_cur * RB + t) * 2 + h) * 32 + l];
                #pragma unroll
                for (int c2 = 0; c2 < 4; ++c2) {
                    const int cc = 4 * h + c2;
                    float u_ = B[cc];
                    float es0 = ex2f(((const float*)&sq[0])[c2] * LOG2E);
                    float es1 = ex2f(((const float*)&sq[1])[c2] * LOG2E);
                    float es2 = ex2f(((const float*)&sq[2])[c2] * LOG2E);
                    float es3 = ex2f(((const float*)&sq[3])[c2] * LOG2E);
                    float es4 = ex2f(((const float*)&sq[4])[c2] * LOG2E);
                    float es5 = ex2f(((const float*)&sq[5])[c2] * LOG2E);
                    float es6 = ex2f(((const float*)&sq[6])[c2] * LOG2E);
                    float es7 = ex2f(((const float*)&sq[7])[c2] * LOG2E);
                    float v0 = fmaf(EG, Lf[0], fmaf(EG, u_, fmaf(es0, dc_,   C)));
                    float v1 = fmaf(EG, Lf[1], fmaf(EG, v0, fmaf(es1, Lf[0], C)));
                    float v2 = fmaf(EG, Lf[2], fmaf(EG, v1, fmaf(es2, Lf[1], C)));
                    float v3 = fmaf(EG, Lf[3], fmaf(EG, v2, fmaf(es3, Lf[2], C)));
                    float v4 = fmaf(EG, Lf[4], fmaf(EG, v3, fmaf(es4, Lf[3], C)));
                    float v5 = fmaf(EG, Lf[5], fmaf(EG, v4, fmaf(es5, Lf[4], C)));
                    float v6 = fmaf(EG, Lf[6], fmaf(EG, v5, fmaf(es6, Lf[5], C)));
                    float v7 = fmaf(EG, Lf[7], fmaf(EG, v6, fmaf(es7, Lf[6], C)));
                    dc_ = u_;
                    B[cc] = valid_ ? v7 : u_;
                    ymx_ = fmaxf(ymx_, fmaxf(fmaxf(fmaxf(v0, v1), fmaxf(v2, v3)),
                                             fmaxf(fmaxf(v4, v5), fmaxf(v6, v7))));
                    Lf[0] = v0; Lf[1] = v1; Lf[2] = v2; Lf[3] = v3;
                    Lf[4] = v4; Lf[5] = v5; Lf[6] = v6; Lf[7] = v7;
                }
            }
            Ymax = fmaxf(Ymax, valid_ ? ymx_ : 0.f);
            { float t7_ = yR[7];
              #pragma unroll
              for (int t = 0; t < 8; ++t) yR[t] = valid_ ? Lf[t] : yR[t];
              y7p = valid_ ? t7_ : y7p; }

            // ---- publish right-column rows (Y) + group K + release flag ----
            if (l == 31 && produce && valid_) {
                const int r0 = RB * (s - 31);
                float4* yp = (float4*)(myedgeY + r0);
                stcg4(yp,     make_float4(Lf[0], Lf[1], Lf[2], Lf[3]));
                stcg4(yp + 1, make_float4(Lf[4], Lf[5], Lf[6], Lf[7]));
                stcg_i(myedgeK + (r0 >> 3), Ki);
                st_rel(myflag, s - 30);
            }

            sl_cur = (sl_cur == 2) ? 0 : sl_cur + 1;
            sl_iss = (sl_iss == 2) ? 0 : sl_iss + 1;
        }
    }

    // ---- final flush + warp reduce + publish (H >= 0) ----
    vh = fmaxf(vh, lg2f(Ymax) + (float)Ki);
    float hv = vh * LN2;
    #pragma unroll
    for (int o = 16; o; o >>= 1)
        hv = fmaxf(hv, __shfl_xor_sync(0xffffffffu, hv, o));
    if (l == 0) atomicMax(&g_max[b], __float_as_int(fmaxf(hv, 0.f)));
#undef ISSUE_SLOT
}

__global__ void sw_final_kernel(float* __restrict__ out, int n) {
    int i = threadIdx.x;
    if (i < n) out[i] = __int_as_float(g_max[i]);
}

extern "C" void kernel_launch(void* const* d_in, const int* in_sizes, int n_in,
                              void* d_out, int out_size) {
    (void)n_in; (void)in_sizes;
    const float* S = (const float*)d_in[0];
    float* out = (float*)d_out;
    const int B = out_size;   // 8

    cudaFuncSetAttribute(sw_wave_kernel,
                         cudaFuncAttributeMaxDynamicSharedMemorySize, SMEM_BYTES);
    sw_init_kernel<<<1, 64>>>();
    sw_wave_kernel<<<NB, 256, SMEM_BYTES>>>(S);
    sw_final_kernel<<<1, 32>>>(out, B);
}